// round 1
// baseline (speedup 1.0000x reference)
#include <cuda_runtime.h>
#include <math.h>

#define B_  32
#define N_  1024
#define D_  256
#define NEGMASK (-9.0e15f)
#define ALPHA_  0.2f

// Scratch (device globals: no allocations allowed in kernel_launch)
__device__ float g_z[B_ * N_ * D_];     // 32 MB
__device__ float g_s1[B_ * N_];
__device__ float g_s2[B_ * N_];

// ---------------------------------------------------------------------------
// Kernel 1: z = h @ W^T + b   (M=32768, N=256, K=256)
// Classic 128x128 block, BK=8, 256 threads, 8x8 per thread.
// ---------------------------------------------------------------------------
__global__ __launch_bounds__(256) void k_zgemm(const float* __restrict__ h,
                                               const float* __restrict__ W,
                                               const float* __restrict__ bias) {
    __shared__ float As[8][128];
    __shared__ float Bs[8][128];
    const int t  = threadIdx.x;
    const int bm = blockIdx.y;   // 0..255
    const int bn = blockIdx.x;   // 0..1
    const int tr = t >> 4, tc = t & 15;
    const int lm = t >> 1, lx = t & 1;

    const float* hA = h + (size_t)(bm * 128 + lm) * D_ + 4 * lx;
    const float* wB = W + (size_t)(bn * 128 + lm) * D_ + 4 * lx;

    float acc[8][8];
#pragma unroll
    for (int i = 0; i < 8; i++)
#pragma unroll
        for (int j = 0; j < 8; j++) acc[i][j] = 0.f;

    for (int k0 = 0; k0 < D_; k0 += 8) {
        float4 av = *(const float4*)(hA + k0);
        float4 bv = *(const float4*)(wB + k0);
        As[4 * lx + 0][lm] = av.x; As[4 * lx + 1][lm] = av.y;
        As[4 * lx + 2][lm] = av.z; As[4 * lx + 3][lm] = av.w;
        Bs[4 * lx + 0][lm] = bv.x; Bs[4 * lx + 1][lm] = bv.y;
        Bs[4 * lx + 2][lm] = bv.z; Bs[4 * lx + 3][lm] = bv.w;
        __syncthreads();
#pragma unroll
        for (int k = 0; k < 8; k++) {
            float ra[8], rb[8];
            *(float4*)&ra[0] = *(const float4*)&As[k][4 * tr];
            *(float4*)&ra[4] = *(const float4*)&As[k][64 + 4 * tr];
            *(float4*)&rb[0] = *(const float4*)&Bs[k][4 * tc];
            *(float4*)&rb[4] = *(const float4*)&Bs[k][64 + 4 * tc];
#pragma unroll
            for (int i = 0; i < 8; i++)
#pragma unroll
                for (int j = 0; j < 8; j++) acc[i][j] += ra[i] * rb[j];
        }
        __syncthreads();
    }

    float bcol[8];
#pragma unroll
    for (int j = 0; j < 4; j++) {
        bcol[j]     = bias[bn * 128 + 4 * tc + j];
        bcol[4 + j] = bias[bn * 128 + 64 + 4 * tc + j];
    }
#pragma unroll
    for (int i = 0; i < 8; i++) {
        int r   = (i < 4) ? (4 * tr + i) : (64 + 4 * tr + (i - 4));
        int row = bm * 128 + r;
        float* zp = g_z + (size_t)row * D_ + bn * 128;
        float4 o0 = make_float4(acc[i][0] + bcol[0], acc[i][1] + bcol[1],
                                acc[i][2] + bcol[2], acc[i][3] + bcol[3]);
        float4 o1 = make_float4(acc[i][4] + bcol[4], acc[i][5] + bcol[5],
                                acc[i][6] + bcol[6], acc[i][7] + bcol[7]);
        *(float4*)(zp + 4 * tc)      = o0;
        *(float4*)(zp + 64 + 4 * tc) = o1;
    }
}

// ---------------------------------------------------------------------------
// Kernel 2: s1 = z . a[:256],  s2 = z . a[256:]   (one warp per row)
// ---------------------------------------------------------------------------
__global__ __launch_bounds__(128) void k_scores(const float* __restrict__ a) {
    int idx  = blockIdx.x * blockDim.x + threadIdx.x;
    int row  = idx >> 5;
    int lane = idx & 31;
    const float* zr = g_z + (size_t)row * D_;
    float a1 = 0.f, a2 = 0.f;
#pragma unroll
    for (int x = 0; x < 8; x++) {
        int d = lane + 32 * x;
        float v = zr[d];
        a1 += v * __ldg(a + d);
        a2 += v * __ldg(a + D_ + d);
    }
#pragma unroll
    for (int o = 16; o > 0; o >>= 1) {
        a1 += __shfl_xor_sync(0xffffffffu, a1, o);
        a2 += __shfl_xor_sync(0xffffffffu, a2, o);
    }
    if (lane == 0) { g_s1[row] = a1; g_s2[row] = a2; }
}

// ---------------------------------------------------------------------------
// Kernel 3: fused masked softmax(rank-1 logits) @ z, with ELU epilogue.
// Block = 64 query rows of one batch. 16 j-tiles of 64. Online softmax.
// smem: zs[64][256] | ps[64][68] | s1s[64] s2s[64] scs[64] ls[64]
// ---------------------------------------------------------------------------
#define SMEM3_FLOATS (64 * 256 + 64 * 68 + 4 * 64)

__global__ __launch_bounds__(256, 2) void k_attn(const int* __restrict__ adj,
                                                 float* __restrict__ out) {
    extern __shared__ float sm[];
    float* zs  = sm;              // [64][256]
    float* ps  = zs + 64 * 256;   // [64][68]  (pad 4 -> 16B-aligned rows)
    float* s1s = ps + 64 * 68;
    float* s2s = s1s + 64;
    float* scs = s2s + 64;
    float* ls  = scs + 64;

    const int b  = blockIdx.y;
    const int i0 = blockIdx.x * 64;
    const int t  = threadIdx.x;
    const int si = t >> 2, sub = t & 3;    // softmax role: 4 threads/row
    const int ti = t >> 5, td = t & 31;    // gemm role: rows 8*ti.., cols 4*td & 128+4*td

    if (t < 64) s1s[t] = g_s1[b * N_ + i0 + t];

    float acc[8][8];
#pragma unroll
    for (int i = 0; i < 8; i++)
#pragma unroll
        for (int j = 0; j < 8; j++) acc[i][j] = 0.f;

    float m_i = -INFINITY, l_i = 0.f;
    const float* zbase = g_z + (size_t)b * N_ * D_;

    for (int j0 = 0; j0 < N_; j0 += 64) {
        __syncthreads();  // previous tile's readers done with zs/ps
        // ---- load z tile (64 x 256) ----
        {
            const float4* src = (const float4*)(zbase + (size_t)j0 * D_);
            float4* dst = (float4*)zs;
#pragma unroll
            for (int r = 0; r < 16; r++) dst[t + 256 * r] = src[t + 256 * r];
        }
        if (t < 64) s2s[t] = g_s2[b * N_ + j0 + t];
        __syncthreads();

        // ---- masked logits + online softmax (4 threads per row) ----
        {
            float s1i = s1s[si];
            const int4* ap = (const int4*)(adj + ((size_t)b * N_ + i0 + si) * N_ + j0 + sub * 16);
            int va[16];
            *(int4*)&va[0]  = ap[0];
            *(int4*)&va[4]  = ap[1];
            *(int4*)&va[8]  = ap[2];
            *(int4*)&va[12] = ap[3];
            float ev[16];
            float mt = -INFINITY;
#pragma unroll
            for (int jj = 0; jj < 16; jj++) {
                float x = s1i + s2s[sub * 16 + jj];
                x = (x >= 0.f) ? x : (ALPHA_ * x);
                float e = (va[jj] > 0) ? x : NEGMASK;
                ev[jj] = e;
                mt = fmaxf(mt, e);
            }
            mt = fmaxf(mt, __shfl_xor_sync(0xffffffffu, mt, 1));
            mt = fmaxf(mt, __shfl_xor_sync(0xffffffffu, mt, 2));
            float m_new = fmaxf(m_i, mt);
            float sc = __expf(m_i - m_new);
            float psum = 0.f;
#pragma unroll
            for (int jj = 0; jj < 16; jj++) {
                float p = __expf(ev[jj] - m_new);
                ps[(sub * 16 + jj) * 68 + si] = p;  // transposed: ps[j][i]
                psum += p;
            }
            psum += __shfl_xor_sync(0xffffffffu, psum, 1);
            psum += __shfl_xor_sync(0xffffffffu, psum, 2);
            l_i = l_i * sc + psum;
            m_i = m_new;
            if (sub == 0) { scs[si] = sc; ls[si] = l_i; }
        }
        __syncthreads();

        // ---- acc = acc*scale + P(64x64) @ Z(64x256), 8x8 per thread ----
        {
#pragma unroll
            for (int ii = 0; ii < 8; ii++) {
                float sc = scs[8 * ti + ii];
#pragma unroll
                for (int cc = 0; cc < 8; cc++) acc[ii][cc] *= sc;
            }
#pragma unroll 4
            for (int j = 0; j < 64; j++) {
                float pa[8], zv[8];
                *(float4*)&pa[0] = *(const float4*)&ps[j * 68 + 8 * ti];       // broadcast
                *(float4*)&pa[4] = *(const float4*)&ps[j * 68 + 8 * ti + 4];
                *(float4*)&zv[0] = *(const float4*)&zs[j * 256 + 4 * td];       // conflict-free
                *(float4*)&zv[4] = *(const float4*)&zs[j * 256 + 128 + 4 * td];
#pragma unroll
                for (int ii = 0; ii < 8; ii++)
#pragma unroll
                    for (int cc = 0; cc < 8; cc++)
                        acc[ii][cc] += pa[ii] * zv[cc];
            }
        }
    }

    // ---- epilogue: divide by l, ELU, store ----
#pragma unroll
    for (int ii = 0; ii < 8; ii++) {
        int row = i0 + 8 * ti + ii;
        float inv = 1.f / ls[8 * ti + ii];
        float v[8];
#pragma unroll
        for (int cc = 0; cc < 8; cc++) {
            float x = acc[ii][cc] * inv;
            v[cc] = (x > 0.f) ? x : expm1f(x);
        }
        float* op = out + ((size_t)b * N_ + row) * D_;
        *(float4*)(op + 4 * td)       = make_float4(v[0], v[1], v[2], v[3]);
        *(float4*)(op + 128 + 4 * td) = make_float4(v[4], v[5], v[6], v[7]);
    }
}

// ---------------------------------------------------------------------------
extern "C" void kernel_launch(void* const* d_in, const int* in_sizes, int n_in,
                              void* d_out, int out_size) {
    const float* h    = (const float*)d_in[0];
    const int*   adj  = (const int*)d_in[1];
    const float* W    = (const float*)d_in[2];
    const float* bias = (const float*)d_in[3];
    const float* a    = (const float*)d_in[4];
    float* out = (float*)d_out;

    (void)in_sizes; (void)n_in; (void)out_size;

    cudaFuncSetAttribute(k_attn, cudaFuncAttributeMaxDynamicSharedMemorySize,
                         SMEM3_FLOATS * sizeof(float));

    k_zgemm<<<dim3(2, 256), 256>>>(h, W, bias);
    k_scores<<<(B_ * N_) / 4, 128>>>(a);
    k_attn<<<dim3(N_ / 64, B_), 256, SMEM3_FLOATS * sizeof(float)>>>(adj, out);
}

// round 3
// speedup vs baseline: 1.5256x; 1.5256x over previous
#include <cuda_runtime.h>
#include <math.h>
#include <stdint.h>

#define B_  32
#define N_  1024
#define D_  256
#define NEGMASK (-9.0e15f)
#define ALPHA_  0.2f

// ---------------- device scratch ----------------
__device__ float g_z [B_ * N_ * D_];     // z  [b][j][d]
__device__ float g_zt[B_ * N_ * D_];     // zt [b][d][j]  (tf32-rounded)
__device__ float g_s1[B_ * N_];
__device__ float g_s2[B_ * N_];
__device__ float g_m [B_ * N_];
__device__ float g_linv[B_ * N_];
__device__ unsigned g_bits[B_ * N_ * 32];  // adj bitmask

// ---------------- helpers ----------------
__device__ __forceinline__ uint32_t smem_u32(const void* p) {
    uint32_t a;
    asm("{ .reg .u64 t; cvta.to.shared.u64 t, %1; cvt.u32.u64 %0, t; }" : "=r"(a) : "l"(p));
    return a;
}
__device__ __forceinline__ uint32_t tf32u(float f) {
    uint32_t u; asm("cvt.rna.tf32.f32 %0, %1;" : "=r"(u) : "f"(f));
    return u;
}
#define CP_ASYNC16(sm, gp) \
    asm volatile("cp.async.cg.shared.global [%0], [%1], 16;" :: "r"(sm), "l"(gp) : "memory")
#define CP_COMMIT()  asm volatile("cp.async.commit_group;" ::: "memory")
#define CP_WAIT0()   asm volatile("cp.async.wait_group 0;" ::: "memory")
#define CP_WAIT1()   asm volatile("cp.async.wait_group 1;" ::: "memory")

__device__ __forceinline__ void mma_tf32(float* c, uint32_t a0, uint32_t a1,
                                         uint32_t a2, uint32_t a3,
                                         uint32_t b0, uint32_t b1) {
    asm volatile(
        "mma.sync.aligned.m16n8k8.row.col.f32.tf32.tf32.f32 "
        "{%0,%1,%2,%3}, {%4,%5,%6,%7}, {%8,%9}, {%0,%1,%2,%3};"
        : "+f"(c[0]), "+f"(c[1]), "+f"(c[2]), "+f"(c[3])
        : "r"(a0), "r"(a1), "r"(a2), "r"(a3), "r"(b0), "r"(b1));
}

// ---------------------------------------------------------------------------
// Kernel 1: z = h @ W^T + b   (fp32 FFMA GEMM, unchanged)
// ---------------------------------------------------------------------------
__global__ __launch_bounds__(256) void k_zgemm(const float* __restrict__ h,
                                               const float* __restrict__ W,
                                               const float* __restrict__ bias) {
    __shared__ float As[8][128];
    __shared__ float Bs[8][128];
    const int t  = threadIdx.x;
    const int bm = blockIdx.y;
    const int bn = blockIdx.x;
    const int tr = t >> 4, tc = t & 15;
    const int lm = t >> 1, lx = t & 1;

    const float* hA = h + (size_t)(bm * 128 + lm) * D_ + 4 * lx;
    const float* wB = W + (size_t)(bn * 128 + lm) * D_ + 4 * lx;

    float acc[8][8];
#pragma unroll
    for (int i = 0; i < 8; i++)
#pragma unroll
        for (int j = 0; j < 8; j++) acc[i][j] = 0.f;

    for (int k0 = 0; k0 < D_; k0 += 8) {
        float4 av = *(const float4*)(hA + k0);
        float4 bv = *(const float4*)(wB + k0);
        As[4 * lx + 0][lm] = av.x; As[4 * lx + 1][lm] = av.y;
        As[4 * lx + 2][lm] = av.z; As[4 * lx + 3][lm] = av.w;
        Bs[4 * lx + 0][lm] = bv.x; Bs[4 * lx + 1][lm] = bv.y;
        Bs[4 * lx + 2][lm] = bv.z; Bs[4 * lx + 3][lm] = bv.w;
        __syncthreads();
#pragma unroll
        for (int k = 0; k < 8; k++) {
            float ra[8], rb[8];
            *(float4*)&ra[0] = *(const float4*)&As[k][4 * tr];
            *(float4*)&ra[4] = *(const float4*)&As[k][64 + 4 * tr];
            *(float4*)&rb[0] = *(const float4*)&Bs[k][4 * tc];
            *(float4*)&rb[4] = *(const float4*)&Bs[k][64 + 4 * tc];
#pragma unroll
            for (int i = 0; i < 8; i++)
#pragma unroll
                for (int j = 0; j < 8; j++) acc[i][j] += ra[i] * rb[j];
        }
        __syncthreads();
    }

    float bcol[8];
#pragma unroll
    for (int j = 0; j < 4; j++) {
        bcol[j]     = bias[bn * 128 + 4 * tc + j];
        bcol[4 + j] = bias[bn * 128 + 64 + 4 * tc + j];
    }
#pragma unroll
    for (int i = 0; i < 8; i++) {
        int r   = (i < 4) ? (4 * tr + i) : (64 + 4 * tr + (i - 4));
        int row = bm * 128 + r;
        float* zp = g_z + (size_t)row * D_ + bn * 128;
        float4 o0 = make_float4(acc[i][0] + bcol[0], acc[i][1] + bcol[1],
                                acc[i][2] + bcol[2], acc[i][3] + bcol[3]);
        float4 o1 = make_float4(acc[i][4] + bcol[4], acc[i][5] + bcol[5],
                                acc[i][6] + bcol[6], acc[i][7] + bcol[7]);
        *(float4*)(zp + 4 * tc)      = o0;
        *(float4*)(zp + 64 + 4 * tc) = o1;
    }
}

// ---------------------------------------------------------------------------
// Kernel 2: s1 = z . a1, s2 = z . a2
// ---------------------------------------------------------------------------
__global__ __launch_bounds__(128) void k_scores(const float* __restrict__ a) {
    int idx  = blockIdx.x * blockDim.x + threadIdx.x;
    int row  = idx >> 5;
    int lane = idx & 31;
    const float* zr = g_z + (size_t)row * D_;
    float a1 = 0.f, a2 = 0.f;
#pragma unroll
    for (int x = 0; x < 8; x++) {
        int d = lane + 32 * x;
        float v = zr[d];
        a1 += v * __ldg(a + d);
        a2 += v * __ldg(a + D_ + d);
    }
#pragma unroll
    for (int o = 16; o > 0; o >>= 1) {
        a1 += __shfl_xor_sync(0xffffffffu, a1, o);
        a2 += __shfl_xor_sync(0xffffffffu, a2, o);
    }
    if (lane == 0) { g_s1[row] = a1; g_s2[row] = a2; }
}

// ---------------------------------------------------------------------------
// Kernel 3: transpose z -> zt[b][d][j], tf32-rounded
// ---------------------------------------------------------------------------
__global__ __launch_bounds__(256) void k_transpose() {
    __shared__ float tile[32][33];
    int b = blockIdx.z, j0 = blockIdx.x << 5, d0 = blockIdx.y << 5;
    int tx = threadIdx.x & 31, ty = threadIdx.x >> 5;
    const float* zb = g_z + ((size_t)b << 18);
#pragma unroll
    for (int q = 0; q < 4; q++)
        tile[ty + 8 * q][tx] = zb[(size_t)(j0 + ty + 8 * q) * D_ + d0 + tx];
    __syncthreads();
    float* zt = g_zt + ((size_t)b << 18);
#pragma unroll
    for (int q = 0; q < 4; q++)
        zt[(size_t)(d0 + ty + 8 * q) * N_ + j0 + tx] =
            __uint_as_float(tf32u(tile[tx][ty + 8 * q]));
}

// ---------------------------------------------------------------------------
// Kernel 4: per-row mask stats: m_i, 1/l_i, packed adj bits. One warp per row.
// ---------------------------------------------------------------------------
__global__ __launch_bounds__(256) void k_maskstat(const int* __restrict__ adj) {
    __shared__ float s2s[N_];
    int row0 = blockIdx.x * 8;
    int b    = row0 >> 10;
    {
        const float4* s = (const float4*)(g_s2 + ((size_t)b << 10));
        ((float4*)s2s)[threadIdx.x] = s[threadIdx.x];
    }
    __syncthreads();
    int w = threadIdx.x >> 5, lane = threadIdx.x & 31;
    int row = row0 + w;
    float s1i = g_s1[row];
    const int* arow = adj + (size_t)row * N_;
    float ev[32];
    float m = -INFINITY;
    uint32_t myword = 0;
#pragma unroll
    for (int k = 0; k < 32; k++) {
        int j = lane + 32 * k;
        int v = arow[j];
        float x = s1i + s2s[j];
        x = (x >= 0.f) ? x : (ALPHA_ * x);
        bool conn = (v > 0);
        uint32_t bal = __ballot_sync(0xffffffffu, conn);
        if (lane == k) myword = bal;
        float e = conn ? x : NEGMASK;
        ev[k] = e;
        m = fmaxf(m, e);
    }
#pragma unroll
    for (int o = 16; o > 0; o >>= 1) m = fmaxf(m, __shfl_xor_sync(0xffffffffu, m, o));
    float l = 0.f;
#pragma unroll
    for (int k = 0; k < 32; k++) l += __expf(ev[k] - m);
#pragma unroll
    for (int o = 16; o > 0; o >>= 1) l += __shfl_xor_sync(0xffffffffu, l, o);
    g_bits[(size_t)row * 32 + lane] = myword;
    if (lane == 0) { g_m[row] = m; g_linv[row] = 1.0f / l; }
}

// ---------------------------------------------------------------------------
// Kernel 5: out = ELU( P @ Z ) via mma.sync tf32. P generated on the fly
// (no rescaling: m/linv precomputed). CTA = 128 i x 128 d, 8 warps of 32x64.
// Loop over 32 j-chunks of 32, Z double-buffered via cp.async.
// smem (floats): ZS0[128][36] | ZS1[128][36] | PS[128][36] | S2[1024]
// ---------------------------------------------------------------------------
#define ZS0_  0
#define ZS1_  4608
#define PS_   9216
#define S2_   13824
#define SMF_  (13824 + 1024)          // 14848 floats = 59392 bytes

__global__ __launch_bounds__(256, 2) void k_attn3(const unsigned* __restrict__ bits,
                                                  float* __restrict__ out) {
    extern __shared__ __align__(16) float sm[];
    const uint32_t sb = smem_u32(sm);
    const uint32_t* smu = (const uint32_t*)sm;

    const int t    = threadIdx.x;
    const int lane = t & 31;
    const int wid  = t >> 5;
    const int wr   = wid & 3;          // row group: rows wr*32 .. +32
    const int wc   = wid >> 2;         // col group: cols wc*64 .. +64
    const int g    = lane >> 2;        // fragment group id
    const int tq   = lane & 3;         // thread-in-group

    const int b  = blockIdx.z;
    const int i0 = blockIdx.x * 128;
    const int d0 = blockIdx.y * 128;

    // load all of s2 for this batch
    ((float4*)(sm + S2_))[t] = ((const float4*)(g_s2 + ((size_t)b << 10)))[t];

    // P-generation role: row pi, col half jh
    const int pi = t >> 1, jh = t & 1;
    const size_t grow = ((size_t)b << 10) + i0 + pi;
    const float s1i  = g_s1[grow];
    const float mi   = g_m[grow];
    const float linv = g_linv[grow];
    const unsigned* brow = bits + grow * 32;

    const char* ztb = (const char*)(g_zt + ((size_t)b << 18));

    float acc[2][8][4];
#pragma unroll
    for (int mt = 0; mt < 2; mt++)
#pragma unroll
        for (int nt = 0; nt < 8; nt++)
#pragma unroll
            for (int q = 0; q < 4; q++) acc[mt][nt][q] = 0.f;

    // cp.async issue for chunk c into buffer buf: rows = local d, 8x16B per row
    const int cdrow = t >> 3, cseg = t & 7;

    // prologue: chunk 0 -> buf 0
#pragma unroll
    for (int q = 0; q < 4; q++) {
        int d = cdrow + 32 * q;
        CP_ASYNC16(sb + (ZS0_ + 0) * 4 + d * 144 + cseg * 16,
                   ztb + (size_t)(d0 + d) * 4096 + cseg * 16);
    }
    CP_COMMIT();
    __syncthreads();

    for (int c = 0; c < 32; c++) {
        // ---- generate P(c) into PS (prev mma readers done: sync at loop end)
        {
            uint32_t word = __ldg(brow + c);
            float* prow = sm + PS_ + pi * 36 + jh * 16;
            const float* s2c = sm + S2_ + c * 32 + jh * 16;
#pragma unroll
            for (int jj = 0; jj < 16; jj += 2) {
                float x0 = s1i + s2c[jj];
                float x1 = s1i + s2c[jj + 1];
                x0 = (x0 >= 0.f) ? x0 : (ALPHA_ * x0);
                x1 = (x1 >= 0.f) ? x1 : (ALPHA_ * x1);
                int jl = jh * 16 + jj;
                float e0 = ((word >> jl) & 1u) ? x0 : NEGMASK;
                float e1 = ((word >> (jl + 1)) & 1u) ? x1 : NEGMASK;
                float2 p;
                p.x = __uint_as_float(tf32u(__expf(e0 - mi) * linv));
                p.y = __uint_as_float(tf32u(__expf(e1 - mi) * linv));
                *(float2*)(prow + jj) = p;
            }
        }
        // ---- prefetch Z(c+1)
        if (c < 31) {
            uint32_t zoff = ((c + 1) & 1) ? ZS1_ : ZS0_;
#pragma unroll
            for (int q = 0; q < 4; q++) {
                int d = cdrow + 32 * q;
                CP_ASYNC16(sb + zoff * 4 + d * 144 + cseg * 16,
                           ztb + (size_t)(d0 + d) * 4096 + (size_t)(c + 1) * 128 + cseg * 16);
            }
            CP_COMMIT();
            CP_WAIT1();
        } else {
            CP_WAIT0();
        }
        __syncthreads();

        // ---- mma: acc += P(128x32) @ Z(32x128), warp tile 32x64
        {
            const uint32_t zofs = ((c & 1) ? ZS1_ : ZS0_);
            const int nb = wc * 64 + g;       // B frag col base (+nt*8)
            const int rb = wr * 32 + g;       // A frag row base (+mt*16)
#pragma unroll
            for (int k0 = 0; k0 < 32; k0 += 8) {
                uint32_t bf[8][2];
#pragma unroll
                for (int nt = 0; nt < 8; nt++) {
                    int base = zofs + (nb + nt * 8) * 36 + k0 + tq;
                    bf[nt][0] = smu[base];
                    bf[nt][1] = smu[base + 4];
                }
#pragma unroll
                for (int mt = 0; mt < 2; mt++) {
                    int ab = PS_ + (rb + mt * 16) * 36 + k0 + tq;
                    uint32_t a0 = smu[ab];
                    uint32_t a1 = smu[ab + 8 * 36];
                    uint32_t a2 = smu[ab + 4];
                    uint32_t a3 = smu[ab + 8 * 36 + 4];
#pragma unroll
                    for (int nt = 0; nt < 8; nt++)
                        mma_tf32(acc[mt][nt], a0, a1, a2, a3, bf[nt][0], bf[nt][1]);
                }
            }
        }
        __syncthreads();
    }

    // ---- epilogue: ELU + store (thread holds rows {g,g+8}, cols {2tq,2tq+1})
#pragma unroll
    for (int mt = 0; mt < 2; mt++) {
        int row0 = i0 + wr * 32 + mt * 16 + g;
        float* o0 = out + (((size_t)b << 10) + row0) * D_ + d0 + wc * 64 + 2 * tq;
        float* o1 = o0 + 8 * D_;
#pragma unroll
        for (int nt = 0; nt < 8; nt++) {
            float v0 = acc[mt][nt][0], v1 = acc[mt][nt][1];
            float v2 = acc[mt][nt][2], v3 = acc[mt][nt][3];
            float2 r0, r1;
            r0.x = (v0 > 0.f) ? v0 : expm1f(v0);
            r0.y = (v1 > 0.f) ? v1 : expm1f(v1);
            r1.x = (v2 > 0.f) ? v2 : expm1f(v2);
            r1.y = (v3 > 0.f) ? v3 : expm1f(v3);
            *(float2*)(o0 + nt * 8) = r0;
            *(float2*)(o1 + nt * 8) = r1;
        }
    }
}

// ---------------------------------------------------------------------------
extern "C" void kernel_launch(void* const* d_in, const int* in_sizes, int n_in,
                              void* d_out, int out_size) {
    const float* h    = (const float*)d_in[0];
    const int*   adj  = (const int*)d_in[1];
    const float* W    = (const float*)d_in[2];
    const float* bias = (const float*)d_in[3];
    const float* a    = (const float*)d_in[4];
    float* out = (float*)d_out;
    (void)in_sizes; (void)n_in; (void)out_size;

    cudaFuncSetAttribute(k_attn3, cudaFuncAttributeMaxDynamicSharedMemorySize,
                         SMF_ * sizeof(float));

    unsigned* bits_p;
    cudaGetSymbolAddress((void**)&bits_p, g_bits);

    k_zgemm<<<dim3(2, 256), 256>>>(h, W, bias);
    k_scores<<<(B_ * N_) / 4, 128>>>(a);
    k_transpose<<<dim3(32, 8, 32), 256>>>();
    k_maskstat<<<(B_ * N_) / 8, 256>>>(adj);
    k_attn3<<<dim3(8, 2, 32), 256, SMF_ * sizeof(float)>>>(bits_p, out);
}

// round 4
// speedup vs baseline: 1.5258x; 1.0002x over previous
#include <cuda_runtime.h>
#include <math.h>
#include <stdint.h>

#define B_  32
#define N_  1024
#define D_  256
#define NEGMASK (-9.0e15f)
#define ALPHA_  0.2f

// ---------------- device scratch ----------------
__device__ float g_z [B_ * N_ * D_];     // z  [b][j][d]
__device__ float g_zt[B_ * N_ * D_];     // zt [b][d][j]  (tf32-rounded)
__device__ float g_s1[B_ * N_];
__device__ float g_s2[B_ * N_];
__device__ float g_m [B_ * N_];
__device__ float g_linv[B_ * N_];
__device__ unsigned g_bits[B_ * N_ * 32];  // adj bitmask

// ---------------- helpers ----------------
__device__ __forceinline__ uint32_t smem_u32(const void* p) {
    uint32_t a;
    asm("{ .reg .u64 t; cvta.to.shared.u64 t, %1; cvt.u32.u64 %0, t; }" : "=r"(a) : "l"(p));
    return a;
}
__device__ __forceinline__ uint32_t tf32u(float f) {
    uint32_t u; asm("cvt.rna.tf32.f32 %0, %1;" : "=r"(u) : "f"(f));
    return u;
}
#define CP_ASYNC16(sm, gp) \
    asm volatile("cp.async.cg.shared.global [%0], [%1], 16;" :: "r"(sm), "l"(gp) : "memory")
#define CP_COMMIT()  asm volatile("cp.async.commit_group;" ::: "memory")
#define CP_WAIT0()   asm volatile("cp.async.wait_group 0;" ::: "memory")
#define CP_WAIT1()   asm volatile("cp.async.wait_group 1;" ::: "memory")

__device__ __forceinline__ void mma_tf32(float* c, uint32_t a0, uint32_t a1,
                                         uint32_t a2, uint32_t a3,
                                         uint32_t b0, uint32_t b1) {
    asm volatile(
        "mma.sync.aligned.m16n8k8.row.col.f32.tf32.tf32.f32 "
        "{%0,%1,%2,%3}, {%4,%5,%6,%7}, {%8,%9}, {%0,%1,%2,%3};"
        : "+f"(c[0]), "+f"(c[1]), "+f"(c[2]), "+f"(c[3])
        : "r"(a0), "r"(a1), "r"(a2), "r"(a3), "r"(b0), "r"(b1));
}

// ---------------------------------------------------------------------------
// Kernel 1: z = h @ W^T + b   (fp32 FFMA GEMM, unchanged)
// ---------------------------------------------------------------------------
__global__ __launch_bounds__(256) void k_zgemm(const float* __restrict__ h,
                                               const float* __restrict__ W,
                                               const float* __restrict__ bias) {
    __shared__ float As[8][128];
    __shared__ float Bs[8][128];
    const int t  = threadIdx.x;
    const int bm = blockIdx.y;
    const int bn = blockIdx.x;
    const int tr = t >> 4, tc = t & 15;
    const int lm = t >> 1, lx = t & 1;

    const float* hA = h + (size_t)(bm * 128 + lm) * D_ + 4 * lx;
    const float* wB = W + (size_t)(bn * 128 + lm) * D_ + 4 * lx;

    float acc[8][8];
#pragma unroll
    for (int i = 0; i < 8; i++)
#pragma unroll
        for (int j = 0; j < 8; j++) acc[i][j] = 0.f;

    for (int k0 = 0; k0 < D_; k0 += 8) {
        float4 av = *(const float4*)(hA + k0);
        float4 bv = *(const float4*)(wB + k0);
        As[4 * lx + 0][lm] = av.x; As[4 * lx + 1][lm] = av.y;
        As[4 * lx + 2][lm] = av.z; As[4 * lx + 3][lm] = av.w;
        Bs[4 * lx + 0][lm] = bv.x; Bs[4 * lx + 1][lm] = bv.y;
        Bs[4 * lx + 2][lm] = bv.z; Bs[4 * lx + 3][lm] = bv.w;
        __syncthreads();
#pragma unroll
        for (int k = 0; k < 8; k++) {
            float ra[8], rb[8];
            *(float4*)&ra[0] = *(const float4*)&As[k][4 * tr];
            *(float4*)&ra[4] = *(const float4*)&As[k][64 + 4 * tr];
            *(float4*)&rb[0] = *(const float4*)&Bs[k][4 * tc];
            *(float4*)&rb[4] = *(const float4*)&Bs[k][64 + 4 * tc];
#pragma unroll
            for (int i = 0; i < 8; i++)
#pragma unroll
                for (int j = 0; j < 8; j++) acc[i][j] += ra[i] * rb[j];
        }
        __syncthreads();
    }

    float bcol[8];
#pragma unroll
    for (int j = 0; j < 4; j++) {
        bcol[j]     = bias[bn * 128 + 4 * tc + j];
        bcol[4 + j] = bias[bn * 128 + 64 + 4 * tc + j];
    }
#pragma unroll
    for (int i = 0; i < 8; i++) {
        int r   = (i < 4) ? (4 * tr + i) : (64 + 4 * tr + (i - 4));
        int row = bm * 128 + r;
        float* zp = g_z + (size_t)row * D_ + bn * 128;
        float4 o0 = make_float4(acc[i][0] + bcol[0], acc[i][1] + bcol[1],
                                acc[i][2] + bcol[2], acc[i][3] + bcol[3]);
        float4 o1 = make_float4(acc[i][4] + bcol[4], acc[i][5] + bcol[5],
                                acc[i][6] + bcol[6], acc[i][7] + bcol[7]);
        *(float4*)(zp + 4 * tc)      = o0;
        *(float4*)(zp + 64 + 4 * tc) = o1;
    }
}

// ---------------------------------------------------------------------------
// Kernel 2: s1 = z . a1, s2 = z . a2
// ---------------------------------------------------------------------------
__global__ __launch_bounds__(128) void k_scores(const float* __restrict__ a) {
    int idx  = blockIdx.x * blockDim.x + threadIdx.x;
    int row  = idx >> 5;
    int lane = idx & 31;
    const float* zr = g_z + (size_t)row * D_;
    float a1 = 0.f, a2 = 0.f;
#pragma unroll
    for (int x = 0; x < 8; x++) {
        int d = lane + 32 * x;
        float v = zr[d];
        a1 += v * __ldg(a + d);
        a2 += v * __ldg(a + D_ + d);
    }
#pragma unroll
    for (int o = 16; o > 0; o >>= 1) {
        a1 += __shfl_xor_sync(0xffffffffu, a1, o);
        a2 += __shfl_xor_sync(0xffffffffu, a2, o);
    }
    if (lane == 0) { g_s1[row] = a1; g_s2[row] = a2; }
}

// ---------------------------------------------------------------------------
// Kernel 3: transpose z -> zt[b][d][j], tf32-rounded
// ---------------------------------------------------------------------------
__global__ __launch_bounds__(256) void k_transpose() {
    __shared__ float tile[32][33];
    int b = blockIdx.z, j0 = blockIdx.x << 5, d0 = blockIdx.y << 5;
    int tx = threadIdx.x & 31, ty = threadIdx.x >> 5;
    const float* zb = g_z + ((size_t)b << 18);
#pragma unroll
    for (int q = 0; q < 4; q++)
        tile[ty + 8 * q][tx] = zb[(size_t)(j0 + ty + 8 * q) * D_ + d0 + tx];
    __syncthreads();
    float* zt = g_zt + ((size_t)b << 18);
#pragma unroll
    for (int q = 0; q < 4; q++)
        zt[(size_t)(d0 + ty + 8 * q) * N_ + j0 + tx] =
            __uint_as_float(tf32u(tile[tx][ty + 8 * q]));
}

// ---------------------------------------------------------------------------
// Kernel 4: per-row mask stats: m_i, 1/l_i, packed adj bits. One warp per row.
// ---------------------------------------------------------------------------
__global__ __launch_bounds__(256) void k_maskstat(const int* __restrict__ adj) {
    __shared__ float s2s[N_];
    int row0 = blockIdx.x * 8;
    int b    = row0 >> 10;
    {
        const float4* s = (const float4*)(g_s2 + ((size_t)b << 10));
        ((float4*)s2s)[threadIdx.x] = s[threadIdx.x];
    }
    __syncthreads();
    int w = threadIdx.x >> 5, lane = threadIdx.x & 31;
    int row = row0 + w;
    float s1i = g_s1[row];
    const int* arow = adj + (size_t)row * N_;
    float ev[32];
    float m = -INFINITY;
    uint32_t myword = 0;
#pragma unroll
    for (int k = 0; k < 32; k++) {
        int j = lane + 32 * k;
        int v = arow[j];
        float x = s1i + s2s[j];
        x = (x >= 0.f) ? x : (ALPHA_ * x);
        bool conn = (v > 0);
        uint32_t bal = __ballot_sync(0xffffffffu, conn);
        if (lane == k) myword = bal;
        float e = conn ? x : NEGMASK;
        ev[k] = e;
        m = fmaxf(m, e);
    }
#pragma unroll
    for (int o = 16; o > 0; o >>= 1) m = fmaxf(m, __shfl_xor_sync(0xffffffffu, m, o));
    float l = 0.f;
#pragma unroll
    for (int k = 0; k < 32; k++) l += __expf(ev[k] - m);
#pragma unroll
    for (int o = 16; o > 0; o >>= 1) l += __shfl_xor_sync(0xffffffffu, l, o);
    g_bits[(size_t)row * 32 + lane] = myword;
    if (lane == 0) { g_m[row] = m; g_linv[row] = 1.0f / l; }
}

// ---------------------------------------------------------------------------
// Kernel 5: out = ELU( P @ Z ) via mma.sync tf32. P generated on the fly
// (no rescaling: m/linv precomputed). CTA = 128 i x 128 d, 8 warps of 32x64.
// Loop over 32 j-chunks of 32, Z double-buffered via cp.async.
// smem (floats): ZS0[128][36] | ZS1[128][36] | PS[128][36] | S2[1024]
// ---------------------------------------------------------------------------
#define ZS0_  0
#define ZS1_  4608
#define PS_   9216
#define S2_   13824
#define SMF_  (13824 + 1024)          // 14848 floats = 59392 bytes

__global__ __launch_bounds__(256, 2) void k_attn3(const unsigned* __restrict__ bits,
                                                  float* __restrict__ out) {
    extern __shared__ __align__(16) float sm[];
    const uint32_t sb = smem_u32(sm);
    const uint32_t* smu = (const uint32_t*)sm;

    const int t    = threadIdx.x;
    const int lane = t & 31;
    const int wid  = t >> 5;
    const int wr   = wid & 3;          // row group: rows wr*32 .. +32
    const int wc   = wid >> 2;         // col group: cols wc*64 .. +64
    const int g    = lane >> 2;        // fragment group id
    const int tq   = lane & 3;         // thread-in-group

    const int b  = blockIdx.z;
    const int i0 = blockIdx.x * 128;
    const int d0 = blockIdx.y * 128;

    // load all of s2 for this batch
    ((float4*)(sm + S2_))[t] = ((const float4*)(g_s2 + ((size_t)b << 10)))[t];

    // P-generation role: row pi, col half jh
    const int pi = t >> 1, jh = t & 1;
    const size_t grow = ((size_t)b << 10) + i0 + pi;
    const float s1i  = g_s1[grow];
    const float mi   = g_m[grow];
    const float linv = g_linv[grow];
    const unsigned* brow = bits + grow * 32;

    const char* ztb = (const char*)(g_zt + ((size_t)b << 18));

    float acc[2][8][4];
#pragma unroll
    for (int mt = 0; mt < 2; mt++)
#pragma unroll
        for (int nt = 0; nt < 8; nt++)
#pragma unroll
            for (int q = 0; q < 4; q++) acc[mt][nt][q] = 0.f;

    // cp.async issue for chunk c into buffer buf: rows = local d, 8x16B per row
    const int cdrow = t >> 3, cseg = t & 7;

    // prologue: chunk 0 -> buf 0
#pragma unroll
    for (int q = 0; q < 4; q++) {
        int d = cdrow + 32 * q;
        CP_ASYNC16(sb + (ZS0_ + 0) * 4 + d * 144 + cseg * 16,
                   ztb + (size_t)(d0 + d) * 4096 + cseg * 16);
    }
    CP_COMMIT();
    __syncthreads();

    for (int c = 0; c < 32; c++) {
        // ---- generate P(c) into PS (prev mma readers done: sync at loop end)
        {
            uint32_t word = __ldg(brow + c);
            float* prow = sm + PS_ + pi * 36 + jh * 16;
            const float* s2c = sm + S2_ + c * 32 + jh * 16;
#pragma unroll
            for (int jj = 0; jj < 16; jj += 2) {
                float x0 = s1i + s2c[jj];
                float x1 = s1i + s2c[jj + 1];
                x0 = (x0 >= 0.f) ? x0 : (ALPHA_ * x0);
                x1 = (x1 >= 0.f) ? x1 : (ALPHA_ * x1);
                int jl = jh * 16 + jj;
                float e0 = ((word >> jl) & 1u) ? x0 : NEGMASK;
                float e1 = ((word >> (jl + 1)) & 1u) ? x1 : NEGMASK;
                float2 p;
                p.x = __uint_as_float(tf32u(__expf(e0 - mi) * linv));
                p.y = __uint_as_float(tf32u(__expf(e1 - mi) * linv));
                *(float2*)(prow + jj) = p;
            }
        }
        // ---- prefetch Z(c+1)
        if (c < 31) {
            uint32_t zoff = ((c + 1) & 1) ? ZS1_ : ZS0_;
#pragma unroll
            for (int q = 0; q < 4; q++) {
                int d = cdrow + 32 * q;
                CP_ASYNC16(sb + zoff * 4 + d * 144 + cseg * 16,
                           ztb + (size_t)(d0 + d) * 4096 + (size_t)(c + 1) * 128 + cseg * 16);
            }
            CP_COMMIT();
            CP_WAIT1();
        } else {
            CP_WAIT0();
        }
        __syncthreads();

        // ---- mma: acc += P(128x32) @ Z(32x128), warp tile 32x64
        {
            const uint32_t zofs = ((c & 1) ? ZS1_ : ZS0_);
            const int nb = wc * 64 + g;       // B frag col base (+nt*8)
            const int rb = wr * 32 + g;       // A frag row base (+mt*16)
#pragma unroll
            for (int k0 = 0; k0 < 32; k0 += 8) {
                uint32_t bf[8][2];
#pragma unroll
                for (int nt = 0; nt < 8; nt++) {
                    int base = zofs + (nb + nt * 8) * 36 + k0 + tq;
                    bf[nt][0] = smu[base];
                    bf[nt][1] = smu[base + 4];
                }
#pragma unroll
                for (int mt = 0; mt < 2; mt++) {
                    int ab = PS_ + (rb + mt * 16) * 36 + k0 + tq;
                    uint32_t a0 = smu[ab];
                    uint32_t a1 = smu[ab + 8 * 36];
                    uint32_t a2 = smu[ab + 4];
                    uint32_t a3 = smu[ab + 8 * 36 + 4];
#pragma unroll
                    for (int nt = 0; nt < 8; nt++)
                        mma_tf32(acc[mt][nt], a0, a1, a2, a3, bf[nt][0], bf[nt][1]);
                }
            }
        }
        __syncthreads();
    }

    // ---- epilogue: ELU + store (thread holds rows {g,g+8}, cols {2tq,2tq+1})
#pragma unroll
    for (int mt = 0; mt < 2; mt++) {
        int row0 = i0 + wr * 32 + mt * 16 + g;
        float* o0 = out + (((size_t)b << 10) + row0) * D_ + d0 + wc * 64 + 2 * tq;
        float* o1 = o0 + 8 * D_;
#pragma unroll
        for (int nt = 0; nt < 8; nt++) {
            float v0 = acc[mt][nt][0], v1 = acc[mt][nt][1];
            float v2 = acc[mt][nt][2], v3 = acc[mt][nt][3];
            float2 r0, r1;
            r0.x = (v0 > 0.f) ? v0 : expm1f(v0);
            r0.y = (v1 > 0.f) ? v1 : expm1f(v1);
            r1.x = (v2 > 0.f) ? v2 : expm1f(v2);
            r1.y = (v3 > 0.f) ? v3 : expm1f(v3);
            *(float2*)(o0 + nt * 8) = r0;
            *(float2*)(o1 + nt * 8) = r1;
        }
    }
}

// ---------------------------------------------------------------------------
extern "C" void kernel_launch(void* const* d_in, const int* in_sizes, int n_in,
                              void* d_out, int out_size) {
    const float* h    = (const float*)d_in[0];
    const int*   adj  = (const int*)d_in[1];
    const float* W    = (const float*)d_in[2];
    const float* bias = (const float*)d_in[3];
    const float* a    = (const float*)d_in[4];
    float* out = (float*)d_out;
    (void)in_sizes; (void)n_in; (void)out_size;

    cudaFuncSetAttribute(k_attn3, cudaFuncAttributeMaxDynamicSharedMemorySize,
                         SMF_ * sizeof(float));

    unsigned* bits_p;
    cudaGetSymbolAddress((void**)&bits_p, g_bits);

    k_zgemm<<<dim3(2, 256), 256>>>(h, W, bias);
    k_scores<<<(B_ * N_) / 4, 128>>>(a);
    k_transpose<<<dim3(32, 8, 32), 256>>>();
    k_maskstat<<<(B_ * N_) / 8, 256>>>(adj);
    k_attn3<<<dim3(8, 2, 32), 256, SMF_ * sizeof(float)>>>(bits_p, out);
}